// round 1
// baseline (speedup 1.0000x reference)
#include <cuda_runtime.h>

#define BATCH 32
#define SEQ   512
#define DD    1024
#define BS_TOT (BATCH * SEQ)   // 16384

// Scratch (static __device__ arrays — allocation-free per harness rules)
__device__ float g_T[(size_t)BS_TOT * DD];   // 64 MiB: T = Daug @ U
__device__ float g_rowlin[BS_TOT];
__device__ float g_collin[BS_TOT];

// ---------------------------------------------------------------------------
// GEMM1: T[m][n] = sum_k Dflat[m][k] * U[k][n]  + U[1024][n]
//   M = 16384, N = 1024, K = 1024
// Tile 64x64, K-tile 16, 256 threads, each thread computes 4 rows x 4 cols.
// A (Dflat) is K-contiguous -> transpose-on-load into As[k][x].
// B (U) is N-contiguous     -> direct coalesced load into Bs[k][n].
// ---------------------------------------------------------------------------
__global__ __launch_bounds__(256)
void gemm1_kernel(const float* __restrict__ Df,
                  const float* __restrict__ U,
                  float* __restrict__ T)
{
    __shared__ __align__(16) float As[16][65];   // [k][x]  (scalar reads)
    __shared__ __align__(16) float Bs[16][68];   // [k][n]  (float4 reads, stride 272B)

    const int tid = threadIdx.x;
    const int tx  = tid & 15;      // -> 4 contiguous n columns: n = nBase + tx*4 + q
    const int ty  = tid >> 4;      // -> 4 strided x rows:       x = xBase + ty + 16*i
    const int xBase = blockIdx.y * 64;
    const int nBase = blockIdx.x * 64;

    // A-tile load indices: 64 rows x 16 k, float4 per thread
    const int la_row = tid >> 2;          // 0..63
    const int la_kg  = (tid & 3) * 4;     // 0,4,8,12
    // B-tile load indices: 16 k-rows x 64 n, float4 per thread
    const int lb_k   = tid >> 4;          // 0..15
    const int lb_ng  = (tid & 15) * 4;    // 0..60

    float acc[4][4] = {};

    for (int k0 = 0; k0 < DD; k0 += 16) {
        float4 a = *reinterpret_cast<const float4*>(
            &Df[(size_t)(xBase + la_row) * DD + (k0 + la_kg)]);
        float4 b = *reinterpret_cast<const float4*>(
            &U[(size_t)(k0 + lb_k) * DD + (nBase + lb_ng)]);

        As[la_kg + 0][la_row] = a.x;
        As[la_kg + 1][la_row] = a.y;
        As[la_kg + 2][la_row] = a.z;
        As[la_kg + 3][la_row] = a.w;
        *reinterpret_cast<float4*>(&Bs[lb_k][lb_ng]) = b;
        __syncthreads();

        #pragma unroll
        for (int k = 0; k < 16; k++) {
            float av[4];
            #pragma unroll
            for (int i = 0; i < 4; i++) av[i] = As[k][ty + 16 * i];
            float4 bv = *reinterpret_cast<const float4*>(&Bs[k][tx * 4]);
            #pragma unroll
            for (int i = 0; i < 4; i++) {
                acc[i][0] = fmaf(av[i], bv.x, acc[i][0]);
                acc[i][1] = fmaf(av[i], bv.y, acc[i][1]);
                acc[i][2] = fmaf(av[i], bv.z, acc[i][2]);
                acc[i][3] = fmaf(av[i], bv.w, acc[i][3]);
            }
        }
        __syncthreads();
    }

    // bias row U[1024][n] (ones-augmentation column of Daug)
    float4 bias = *reinterpret_cast<const float4*>(
        &U[(size_t)DD * DD + (nBase + tx * 4)]);

    #pragma unroll
    for (int i = 0; i < 4; i++) {
        const int x = xBase + ty + 16 * i;
        float4 o;
        o.x = acc[i][0] + bias.x;
        o.y = acc[i][1] + bias.y;
        o.z = acc[i][2] + bias.z;
        o.w = acc[i][3] + bias.w;
        *reinterpret_cast<float4*>(&T[(size_t)x * DD + (nBase + tx * 4)]) = o;
    }
}

// ---------------------------------------------------------------------------
// LIN: rowlin[m] = D[m]·W[0:1024] + W[1024];  collin[m] = H[m]·W[1025:2049]
// One block (256 threads) per row m.
// ---------------------------------------------------------------------------
__global__ __launch_bounds__(256)
void lin_kernel(const float* __restrict__ Df,
                const float* __restrict__ Hf,
                const float* __restrict__ W,
                float* __restrict__ rowlin,
                float* __restrict__ collin)
{
    const int m = blockIdx.x;
    const int t = threadIdx.x;
    const float* drow = Df + (size_t)m * DD;
    const float* hrow = Hf + (size_t)m * DD;

    float s1 = 0.f, s2 = 0.f;
    for (int k = t; k < DD; k += 256) {
        s1 = fmaf(drow[k], W[k], s1);
        s2 = fmaf(hrow[k], W[DD + 1 + k], s2);
    }
    // warp reduce
    #pragma unroll
    for (int o = 16; o > 0; o >>= 1) {
        s1 += __shfl_down_sync(0xffffffffu, s1, o);
        s2 += __shfl_down_sync(0xffffffffu, s2, o);
    }
    __shared__ float r1[8], r2[8];
    if ((t & 31) == 0) { r1[t >> 5] = s1; r2[t >> 5] = s2; }
    __syncthreads();
    if (t == 0) {
        float a = 0.f, b = 0.f;
        #pragma unroll
        for (int w = 0; w < 8; w++) { a += r1[w]; b += r2[w]; }
        rowlin[m] = a + W[DD];
        collin[m] = b;
    }
}

// ---------------------------------------------------------------------------
// GEMM2 (batched A·B^T): out[b][x][y] = sum_k T[b*512+x][k] * H[b*512+y][k]
//                                        + rowlin[b*512+x] + collin[b*512+y]
// Per batch: M = N = 512, K = 1024. Both operands K-contiguous -> both
// transpose-on-load. Tile 64x64, K-tile 16, 256 threads, 4x4 per thread.
// ---------------------------------------------------------------------------
__global__ __launch_bounds__(256)
void gemm2_kernel(const float* __restrict__ T,
                  const float* __restrict__ Hf,
                  const float* __restrict__ rowlin,
                  const float* __restrict__ collin,
                  float* __restrict__ out)
{
    __shared__ __align__(16) float As[16][65];   // [k][x]  scalar reads
    __shared__ __align__(16) float Bs[16][68];   // [k][y]  float4 reads

    const int tid = threadIdx.x;
    const int tx  = tid & 15;      // y = yBase + tx*4 + q
    const int ty  = tid >> 4;      // x = xBase + ty + 16*i
    const int b     = blockIdx.z;
    const int xBase = blockIdx.y * 64;
    const int yBase = blockIdx.x * 64;

    const int l_row = tid >> 2;         // 0..63
    const int l_kg  = (tid & 3) * 4;    // 0,4,8,12

    const float* Arows = T  + (size_t)(b * SEQ + xBase) * DD;
    const float* Brows = Hf + (size_t)(b * SEQ + yBase) * DD;

    float acc[4][4] = {};

    for (int k0 = 0; k0 < DD; k0 += 16) {
        float4 a = *reinterpret_cast<const float4*>(
            &Arows[(size_t)l_row * DD + (k0 + l_kg)]);
        float4 bq = *reinterpret_cast<const float4*>(
            &Brows[(size_t)l_row * DD + (k0 + l_kg)]);

        As[l_kg + 0][l_row] = a.x;
        As[l_kg + 1][l_row] = a.y;
        As[l_kg + 2][l_row] = a.z;
        As[l_kg + 3][l_row] = a.w;
        Bs[l_kg + 0][l_row] = bq.x;
        Bs[l_kg + 1][l_row] = bq.y;
        Bs[l_kg + 2][l_row] = bq.z;
        Bs[l_kg + 3][l_row] = bq.w;
        __syncthreads();

        #pragma unroll
        for (int k = 0; k < 16; k++) {
            float av[4];
            #pragma unroll
            for (int i = 0; i < 4; i++) av[i] = As[k][ty + 16 * i];
            float4 bv = *reinterpret_cast<const float4*>(&Bs[k][tx * 4]);
            #pragma unroll
            for (int i = 0; i < 4; i++) {
                acc[i][0] = fmaf(av[i], bv.x, acc[i][0]);
                acc[i][1] = fmaf(av[i], bv.y, acc[i][1]);
                acc[i][2] = fmaf(av[i], bv.z, acc[i][2]);
                acc[i][3] = fmaf(av[i], bv.w, acc[i][3]);
            }
        }
        __syncthreads();
    }

    // epilogue: + rowlin[x] + collin[y]
    float4 cl = *reinterpret_cast<const float4*>(
        &collin[b * SEQ + yBase + tx * 4]);

    #pragma unroll
    for (int i = 0; i < 4; i++) {
        const int x = xBase + ty + 16 * i;
        const float rl = rowlin[b * SEQ + x];
        float4 o;
        o.x = acc[i][0] + rl + cl.x;
        o.y = acc[i][1] + rl + cl.y;
        o.z = acc[i][2] + rl + cl.z;
        o.w = acc[i][3] + rl + cl.w;
        *reinterpret_cast<float4*>(
            &out[((size_t)(b * SEQ + x)) * SEQ + (yBase + tx * 4)]) = o;
    }
}

// ---------------------------------------------------------------------------
extern "C" void kernel_launch(void* const* d_in, const int* in_sizes, int n_in,
                              void* d_out, int out_size)
{
    const float* D = (const float*)d_in[0];   // [32,512,1024]
    const float* H = (const float*)d_in[1];   // [32,512,1024]
    const float* U = (const float*)d_in[2];   // [1025,1024]
    const float* W = (const float*)d_in[3];   // [2049]
    float* out = (float*)d_out;               // [32,512,512]

    float* T;      cudaGetSymbolAddress((void**)&T,      g_T);
    float* rowlin; cudaGetSymbolAddress((void**)&rowlin, g_rowlin);
    float* collin; cudaGetSymbolAddress((void**)&collin, g_collin);

    // GEMM1: T = Daug @ U      grid: (N/64, M/64) = (16, 256)
    gemm1_kernel<<<dim3(DD / 64, BS_TOT / 64), 256>>>(D, U, T);

    // linear terms
    lin_kernel<<<BS_TOT, 256>>>(D, H, W, rowlin, collin);

    // GEMM2: out = T @ H^T + rowlin + collin   grid: (8, 8, 32)
    gemm2_kernel<<<dim3(SEQ / 64, SEQ / 64, BATCH), 256>>>(T, H, rowlin, collin, out);
}

// round 3
// speedup vs baseline: 3.5235x; 3.5235x over previous
#include <cuda_runtime.h>
#include <cuda_bf16.h>
#include <cstdint>

#define BATCH 32
#define SEQ   512
#define DD    1024
#define BS_TOT (BATCH*SEQ)      // 16384
#define LDK   2048              // split row stride: hi at [0,1024), lo at [1024,2048)
#define TM    128
#define TN    128
#define KTILE 64
#define NCHUNK (DD/KTILE)       // 16
#define THREADS 256

// SMEM: per stage A(hi,lo) 32KB + B(hi,lo) 32KB = 64KB; 2 stages = 128KB
#define STAGE_BYTES 65536
#define SMEM_TOTAL  (2*STAGE_BYTES)

// ---------------- scratch (static __device__, allocation-free) ----------------
__device__ __nv_bfloat16 g_Ds [(size_t)BS_TOT * LDK];
__device__ __nv_bfloat16 g_Hs [(size_t)BS_TOT * LDK];
__device__ __nv_bfloat16 g_Ts [(size_t)BS_TOT * LDK];
__device__ __nv_bfloat16 g_Uts[(size_t)DD     * LDK];
__device__ float g_rowlin[BS_TOT];
__device__ float g_collin[BS_TOT];

// ---------------- PTX helpers (family-portable: sm_80+) ----------------
#define CP_ASYNC16(smem_u32, gptr) \
    asm volatile("cp.async.cg.shared.global [%0], [%1], 16;" :: "r"(smem_u32), "l"(gptr))
#define CP_COMMIT()  asm volatile("cp.async.commit_group;" ::: "memory")
#define CP_WAIT0()   asm volatile("cp.async.wait_group 0;" ::: "memory")
#define CP_WAIT1()   asm volatile("cp.async.wait_group 1;" ::: "memory")

#define LDSM4(r0,r1,r2,r3,addr) \
    asm volatile("ldmatrix.sync.aligned.m8n8.x4.shared.b16 {%0,%1,%2,%3}, [%4];" \
        : "=r"(r0),"=r"(r1),"=r"(r2),"=r"(r3) : "r"(addr))

#define MMA16816(d, a, b0, b1) \
    asm volatile("mma.sync.aligned.m16n8k16.row.col.f32.bf16.bf16.f32 " \
        "{%0,%1,%2,%3}, {%4,%5,%6,%7}, {%8,%9}, {%0,%1,%2,%3};" \
        : "+f"((d)[0]),"+f"((d)[1]),"+f"((d)[2]),"+f"((d)[3]) \
        : "r"((a)[0]),"r"((a)[1]),"r"((a)[2]),"r"((a)[3]),"r"((b0)),"r"((b1)))

__device__ __forceinline__ uint32_t smem_u32_of(const void* p) {
    uint32_t a;
    asm("{ .reg .u64 t; cvta.to.shared.u64 t, %1; cvt.u32.u64 %0, t; }" : "=r"(a) : "l"(p));
    return a;
}

// ---------------------------------------------------------------------------
// cp.async tile loader: A tile 128 rows x 64 bf16 (hi+lo), B tile same.
// SW128 swizzle: addr = row*128 + (kb ^ ((row&7)<<4)) — store & ldmatrix agree.
// ---------------------------------------------------------------------------
__device__ __forceinline__ void load_tiles(uint32_t sA, uint32_t sB,
    const __nv_bfloat16* __restrict__ A, const __nv_bfloat16* __restrict__ B, int c)
{
    const int tid = threadIdx.x;
    #pragma unroll
    for (int i = 0; i < 4; ++i) {
        int idx = tid + i * THREADS;          // 0..1023
        int row = idx >> 3, j = idx & 7;      // 128 rows x 8 (16B each)
        uint32_t d = (uint32_t)(row * 128 + ((j * 16) ^ ((row & 7) << 4)));
        const __nv_bfloat16* a = A + (size_t)row * LDK + c * KTILE + j * 8;
        const __nv_bfloat16* b = B + (size_t)row * LDK + c * KTILE + j * 8;
        CP_ASYNC16(sA + d,          a);
        CP_ASYNC16(sA + 16384 + d,  a + 1024);
        CP_ASYNC16(sB + d,          b);
        CP_ASYNC16(sB + 16384 + d,  b + 1024);
    }
}

// ---------------------------------------------------------------------------
// Mainloop: acc[fm][fn][4] += split(A[128xK]) * split(B[128xK])^T
// 8 warps as 2(m) x 4(n); warp tile 64m x 32n; 3 split passes (hh, lh, hl).
// ---------------------------------------------------------------------------
__device__ __forceinline__ void hmma_mainloop(uint32_t smem_base,
    const __nv_bfloat16* __restrict__ Arows,
    const __nv_bfloat16* __restrict__ Brows,
    float acc[4][4][4])
{
    const int tid  = threadIdx.x;
    const int lane = tid & 31, wid = tid >> 5;
    const int wm = wid >> 2, wn = wid & 3;

    // ldmatrix per-lane address constants
    const uint32_t aOff  = (uint32_t)((wm * 64 + (lane & 15)) * 128);
    const uint32_t aKb   = (uint32_t)((lane >> 4) * 16);
    const uint32_t bOff  = (uint32_t)((wn * 32 + ((lane >> 4) << 3) + (lane & 7)) * 128);
    const uint32_t bKb   = (uint32_t)(((lane >> 3) & 1) * 16);
    const uint32_t swz   = (uint32_t)((lane & 7) << 4);

    load_tiles(smem_base, smem_base + 32768, Arows, Brows, 0);
    CP_COMMIT();

    for (int c = 0; c < NCHUNK; ++c) {
        if (c + 1 < NCHUNK) {
            uint32_t st = smem_base + ((c + 1) & 1) * STAGE_BYTES;
            load_tiles(st, st + 32768, Arows, Brows, c + 1);
            CP_COMMIT();
            CP_WAIT1();
        } else {
            CP_WAIT0();
        }
        __syncthreads();

        const uint32_t bufA = smem_base + (c & 1) * STAGE_BYTES;
        const uint32_t bufB = bufA + 32768;

        #pragma unroll
        for (int ks = 0; ks < 4; ++ks) {
            uint32_t ahi[4][4], alo[4][4], bhi[2][4], blo[2][4];
            const uint32_t ak = (uint32_t)(ks * 32 + aKb) ^ swz;
            const uint32_t bk = (uint32_t)(ks * 32 + bKb) ^ swz;
            #pragma unroll
            for (int fm = 0; fm < 4; ++fm) {
                uint32_t ad = bufA + aOff + fm * 2048 + ak;
                LDSM4(ahi[fm][0], ahi[fm][1], ahi[fm][2], ahi[fm][3], ad);
                LDSM4(alo[fm][0], alo[fm][1], alo[fm][2], alo[fm][3], ad + 16384);
            }
            #pragma unroll
            for (int g = 0; g < 2; ++g) {
                uint32_t bd = bufB + bOff + g * 2048 + bk;
                LDSM4(bhi[g][0], bhi[g][1], bhi[g][2], bhi[g][3], bd);
                LDSM4(blo[g][0], blo[g][1], blo[g][2], blo[g][3], bd + 16384);
            }
            #pragma unroll
            for (int fm = 0; fm < 4; ++fm) {
                #pragma unroll
                for (int fn = 0; fn < 4; ++fn) {
                    const int g = fn >> 1, p = (fn & 1) * 2;
                    MMA16816(acc[fm][fn], ahi[fm], bhi[g][p], bhi[g][p + 1]);
                    MMA16816(acc[fm][fn], alo[fm], bhi[g][p], bhi[g][p + 1]);
                    MMA16816(acc[fm][fn], ahi[fm], blo[g][p], blo[g][p + 1]);
                }
            }
        }
        __syncthreads();
    }
}

// ---------------------------------------------------------------------------
// GEMM1: T = Daug @ U; epilogue adds bias (U row 1024) and re-splits to hi/lo.
// grid: (DD/TN = 8, BS_TOT/TM = 128)
// ---------------------------------------------------------------------------
__global__ __launch_bounds__(THREADS, 1)
void gemm1_tc(const __nv_bfloat16* __restrict__ A, const __nv_bfloat16* __restrict__ B,
              const float* __restrict__ Ubias, __nv_bfloat16* __restrict__ Tout)
{
    extern __shared__ char smem[];
    uint32_t smem_base = smem_u32_of(smem);

    const size_t mBase = (size_t)blockIdx.y * TM;
    const size_t nBase = (size_t)blockIdx.x * TN;

    float acc[4][4][4] = {};
    hmma_mainloop(smem_base, A + mBase * LDK, B + nBase * LDK, acc);

    const int lane = threadIdx.x & 31, wid = threadIdx.x >> 5;
    const int wm = wid >> 2, wn = wid & 3;

    #pragma unroll
    for (int fm = 0; fm < 4; ++fm) {
        const size_t r0 = mBase + wm * 64 + fm * 16 + (lane >> 2);
        #pragma unroll
        for (int fn = 0; fn < 4; ++fn) {
            const size_t n = nBase + wn * 32 + fn * 8 + 2 * (lane & 3);
            const float b0 = Ubias[n], b1 = Ubias[n + 1];
            #pragma unroll
            for (int h = 0; h < 2; ++h) {
                const size_t r = r0 + h * 8;
                float f0 = acc[fm][fn][2 * h]     + b0;
                float f1 = acc[fm][fn][2 * h + 1] + b1;
                __nv_bfloat16 h0 = __float2bfloat16_rn(f0);
                __nv_bfloat16 h1 = __float2bfloat16_rn(f1);
                __nv_bfloat16 l0 = __float2bfloat16_rn(f0 - __bfloat162float(h0));
                __nv_bfloat16 l1 = __float2bfloat16_rn(f1 - __bfloat162float(h1));
                uint32_t ph = (uint32_t)__bfloat16_as_ushort(h0) | ((uint32_t)__bfloat16_as_ushort(h1) << 16);
                uint32_t pl = (uint32_t)__bfloat16_as_ushort(l0) | ((uint32_t)__bfloat16_as_ushort(l1) << 16);
                *(uint32_t*)(Tout + r * LDK + n)        = ph;
                *(uint32_t*)(Tout + r * LDK + 1024 + n) = pl;
            }
        }
    }
}

// ---------------------------------------------------------------------------
// GEMM2: out[b,x,y] = T[b,x,:].H[b,y,:] + rowlin[b,x] + collin[b,y]
// grid: (SEQ/TN = 4, SEQ/TM = 4, BATCH)
// ---------------------------------------------------------------------------
__global__ __launch_bounds__(THREADS, 1)
void gemm2_tc(const __nv_bfloat16* __restrict__ A, const __nv_bfloat16* __restrict__ B,
              const float* __restrict__ rowlin, const float* __restrict__ collin,
              float* __restrict__ out)
{
    extern __shared__ char smem[];
    uint32_t smem_base = smem_u32_of(smem);

    const int b = blockIdx.z;
    const size_t xBase = (size_t)blockIdx.y * TM;
    const size_t yBase = (size_t)blockIdx.x * TN;

    float acc[4][4][4] = {};
    hmma_mainloop(smem_base,
                  A + ((size_t)b * SEQ + xBase) * LDK,
                  B + ((size_t)b * SEQ + yBase) * LDK, acc);

    const int lane = threadIdx.x & 31, wid = threadIdx.x >> 5;
    const int wm = wid >> 2, wn = wid & 3;

    #pragma unroll
    for (int fm = 0; fm < 4; ++fm) {
        const size_t x0 = xBase + wm * 64 + fm * 16 + (lane >> 2);
        #pragma unroll
        for (int h = 0; h < 2; ++h) {
            const size_t gx = (size_t)b * SEQ + x0 + h * 8;
            const float rl = rowlin[gx];
            #pragma unroll
            for (int fn = 0; fn < 4; ++fn) {
                const size_t y = yBase + wn * 32 + fn * 8 + 2 * (lane & 3);
                const float c0 = collin[(size_t)b * SEQ + y];
                const float c1 = collin[(size_t)b * SEQ + y + 1];
                float2 o;
                o.x = acc[fm][fn][2 * h]     + rl + c0;
                o.y = acc[fm][fn][2 * h + 1] + rl + c1;
                *(float2*)(out + gx * SEQ + y) = o;
            }
        }
    }
}

// ---------------------------------------------------------------------------
// Prep kernels
// ---------------------------------------------------------------------------
__global__ __launch_bounds__(256)
void split_kernel(const float* __restrict__ src, __nv_bfloat16* __restrict__ dst)
{
    size_t i = (size_t)blockIdx.x * 256 + threadIdx.x;   // over 4M float4
    float4 v = ((const float4*)src)[i];
    size_t row = i >> 8;
    size_t c4  = (i & 255) * 4;
    float f[4] = {v.x, v.y, v.z, v.w};
    uint32_t hw[2], lw[2];
    #pragma unroll
    for (int p = 0; p < 2; ++p) {
        __nv_bfloat16 h0 = __float2bfloat16_rn(f[2*p]);
        __nv_bfloat16 h1 = __float2bfloat16_rn(f[2*p+1]);
        __nv_bfloat16 l0 = __float2bfloat16_rn(f[2*p]   - __bfloat162float(h0));
        __nv_bfloat16 l1 = __float2bfloat16_rn(f[2*p+1] - __bfloat162float(h1));
        hw[p] = (uint32_t)__bfloat16_as_ushort(h0) | ((uint32_t)__bfloat16_as_ushort(h1) << 16);
        lw[p] = (uint32_t)__bfloat16_as_ushort(l0) | ((uint32_t)__bfloat16_as_ushort(l1) << 16);
    }
    *(uint2*)(dst + row * LDK + c4)        = make_uint2(hw[0], hw[1]);
    *(uint2*)(dst + row * LDK + 1024 + c4) = make_uint2(lw[0], lw[1]);
}

__global__ __launch_bounds__(256)
void transU_kernel(const float* __restrict__ U, __nv_bfloat16* __restrict__ Ut)
{
    __shared__ float t[32][33];
    const int k0 = blockIdx.y * 32, n0 = blockIdx.x * 32;
    const int tx = threadIdx.x, ty = threadIdx.y;   // block (32, 8)
    #pragma unroll
    for (int i = ty; i < 32; i += 8)
        t[i][tx] = U[(size_t)(k0 + i) * DD + n0 + tx];
    __syncthreads();
    #pragma unroll
    for (int i = ty; i < 32; i += 8) {
        const size_t n = n0 + i, k = k0 + tx;
        float f = t[tx][i];
        __nv_bfloat16 h = __float2bfloat16_rn(f);
        __nv_bfloat16 l = __float2bfloat16_rn(f - __bfloat162float(h));
        Ut[n * LDK + k]        = h;
        Ut[n * LDK + 1024 + k] = l;
    }
}

__global__ __launch_bounds__(256)
void lin_kernel(const float* __restrict__ Df, const float* __restrict__ Hf,
                const float* __restrict__ W,
                float* __restrict__ rowlin, float* __restrict__ collin)
{
    const int m = blockIdx.x;
    const int t = threadIdx.x;
    const float* drow = Df + (size_t)m * DD;
    const float* hrow = Hf + (size_t)m * DD;
    float s1 = 0.f, s2 = 0.f;
    for (int k = t; k < DD; k += 256) {
        s1 = fmaf(drow[k], W[k], s1);
        s2 = fmaf(hrow[k], W[DD + 1 + k], s2);
    }
    #pragma unroll
    for (int o = 16; o > 0; o >>= 1) {
        s1 += __shfl_down_sync(0xffffffffu, s1, o);
        s2 += __shfl_down_sync(0xffffffffu, s2, o);
    }
    __shared__ float r1[8], r2[8];
    if ((t & 31) == 0) { r1[t >> 5] = s1; r2[t >> 5] = s2; }
    __syncthreads();
    if (t == 0) {
        float a = 0.f, bb = 0.f;
        #pragma unroll
        for (int ww = 0; ww < 8; ww++) { a += r1[ww]; bb += r2[ww]; }
        rowlin[m] = a + W[DD];
        collin[m] = bb;
    }
}

// ---------------------------------------------------------------------------
extern "C" void kernel_launch(void* const* d_in, const int* in_sizes, int n_in,
                              void* d_out, int out_size)
{
    const float* D = (const float*)d_in[0];   // [32,512,1024]
    const float* H = (const float*)d_in[1];   // [32,512,1024]
    const float* U = (const float*)d_in[2];   // [1025,1024]
    const float* W = (const float*)d_in[3];   // [2049]
    float* out = (float*)d_out;               // [32,512,512]

    __nv_bfloat16 *Ds, *Hs, *Ts, *Uts;
    float *rowlin, *collin;
    cudaGetSymbolAddress((void**)&Ds,  g_Ds);
    cudaGetSymbolAddress((void**)&Hs,  g_Hs);
    cudaGetSymbolAddress((void**)&Ts,  g_Ts);
    cudaGetSymbolAddress((void**)&Uts, g_Uts);
    cudaGetSymbolAddress((void**)&rowlin, g_rowlin);
    cudaGetSymbolAddress((void**)&collin, g_collin);

    cudaFuncSetAttribute(gemm1_tc, cudaFuncAttributeMaxDynamicSharedMemorySize, SMEM_TOTAL);
    cudaFuncSetAttribute(gemm2_tc, cudaFuncAttributeMaxDynamicSharedMemorySize, SMEM_TOTAL);

    // prep
    split_kernel<<<(BS_TOT * (size_t)DD / 4) / 256, 256>>>(D, Ds);
    split_kernel<<<(BS_TOT * (size_t)DD / 4) / 256, 256>>>(H, Hs);
    transU_kernel<<<dim3(32, 32), dim3(32, 8)>>>(U, Uts);
    lin_kernel<<<BS_TOT, 256>>>(D, H, W, rowlin, collin);

    // GEMM1: T = Daug @ U
    gemm1_tc<<<dim3(DD / TN, BS_TOT / TM), THREADS, SMEM_TOTAL>>>(
        Ds, Uts, U + (size_t)DD * DD, Ts);

    // GEMM2: out = T @ H^T + rowlin + collin
    gemm2_tc<<<dim3(SEQ / TN, SEQ / TM, BATCH), THREADS, SMEM_TOTAL>>>(
        Ts, Hs, rowlin, collin, out);
}

// round 4
// speedup vs baseline: 3.8615x; 1.0959x over previous
#include <cuda_runtime.h>
#include <cuda_bf16.h>
#include <cstdint>

#define BATCH 32
#define SEQ   512
#define DD    1024
#define BS_TOT (BATCH*SEQ)      // 16384
#define LDK   2048              // split row stride: hi at [0,1024), lo at [1024,2048)
#define TM    128
#define TN    128
#define KTILE 64
#define NCHUNK (DD/KTILE)       // 16
#define THREADS 256

// SMEM: per stage A(hi,lo) 32KB + B(hi,lo) 32KB = 64KB; 2 stages = 128KB
#define STAGE_BYTES 65536
#define SMEM_TOTAL  (2*STAGE_BYTES)

// ---------------- scratch (static __device__, allocation-free) ----------------
__device__ __nv_bfloat16 g_Ds [(size_t)BS_TOT * LDK];
__device__ __nv_bfloat16 g_Hs [(size_t)BS_TOT * LDK];
__device__ __nv_bfloat16 g_Ts [(size_t)BS_TOT * LDK];
__device__ __nv_bfloat16 g_Uts[(size_t)DD     * LDK];
__device__ float g_rowlin[BS_TOT];
__device__ float g_collin[BS_TOT];

// ---------------- PTX helpers (family-portable: sm_80+) ----------------
#define CP_ASYNC16(smem_u32, gptr) \
    asm volatile("cp.async.cg.shared.global [%0], [%1], 16;" :: "r"(smem_u32), "l"(gptr))
#define CP_COMMIT()  asm volatile("cp.async.commit_group;" ::: "memory")
#define CP_WAIT0()   asm volatile("cp.async.wait_group 0;" ::: "memory")
#define CP_WAIT1()   asm volatile("cp.async.wait_group 1;" ::: "memory")

#define LDSM4(r0,r1,r2,r3,addr) \
    asm volatile("ldmatrix.sync.aligned.m8n8.x4.shared.b16 {%0,%1,%2,%3}, [%4];" \
        : "=r"(r0),"=r"(r1),"=r"(r2),"=r"(r3) : "r"(addr))

#define MMA16816(d, a, b0, b1) \
    asm volatile("mma.sync.aligned.m16n8k16.row.col.f32.bf16.bf16.f32 " \
        "{%0,%1,%2,%3}, {%4,%5,%6,%7}, {%8,%9}, {%0,%1,%2,%3};" \
        : "+f"((d)[0]),"+f"((d)[1]),"+f"((d)[2]),"+f"((d)[3]) \
        : "r"((a)[0]),"r"((a)[1]),"r"((a)[2]),"r"((a)[3]),"r"((b0)),"r"((b1)))

__device__ __forceinline__ uint32_t smem_u32_of(const void* p) {
    uint32_t a;
    asm("{ .reg .u64 t; cvta.to.shared.u64 t, %1; cvt.u32.u64 %0, t; }" : "=r"(a) : "l"(p));
    return a;
}

__device__ __forceinline__ uint32_t pack_hi2(float f0, float f1,
                                             __nv_bfloat16& h0, __nv_bfloat16& h1) {
    h0 = __float2bfloat16_rn(f0);
    h1 = __float2bfloat16_rn(f1);
    return (uint32_t)__bfloat16_as_ushort(h0) | ((uint32_t)__bfloat16_as_ushort(h1) << 16);
}
__device__ __forceinline__ uint32_t pack_lo2(float f0, float f1,
                                             __nv_bfloat16 h0, __nv_bfloat16 h1) {
    __nv_bfloat16 l0 = __float2bfloat16_rn(f0 - __bfloat162float(h0));
    __nv_bfloat16 l1 = __float2bfloat16_rn(f1 - __bfloat162float(h1));
    return (uint32_t)__bfloat16_as_ushort(l0) | ((uint32_t)__bfloat16_as_ushort(l1) << 16);
}

__device__ __forceinline__ void store_split4(__nv_bfloat16* dst, float4 v) {
    __nv_bfloat16 h0, h1, h2, h3;
    uint32_t hA = pack_hi2(v.x, v.y, h0, h1);
    uint32_t hB = pack_hi2(v.z, v.w, h2, h3);
    uint32_t lA = pack_lo2(v.x, v.y, h0, h1);
    uint32_t lB = pack_lo2(v.z, v.w, h2, h3);
    *(uint2*)dst          = make_uint2(hA, hB);
    *(uint2*)(dst + 1024) = make_uint2(lA, lB);
}

// ---------------------------------------------------------------------------
// cp.async tile loader: A tile 128 rows x 64 bf16 (hi+lo), B tile same.
// SW128 swizzle: addr = row*128 + (kb ^ ((row&7)<<4)) — store & ldmatrix agree.
// ---------------------------------------------------------------------------
__device__ __forceinline__ void load_tiles(uint32_t sA, uint32_t sB,
    const __nv_bfloat16* __restrict__ A, const __nv_bfloat16* __restrict__ B, int c)
{
    const int tid = threadIdx.x;
    #pragma unroll
    for (int i = 0; i < 4; ++i) {
        int idx = tid + i * THREADS;          // 0..1023
        int row = idx >> 3, j = idx & 7;      // 128 rows x 8 (16B each)
        uint32_t d = (uint32_t)(row * 128 + ((j * 16) ^ ((row & 7) << 4)));
        const __nv_bfloat16* a = A + (size_t)row * LDK + c * KTILE + j * 8;
        const __nv_bfloat16* b = B + (size_t)row * LDK + c * KTILE + j * 8;
        CP_ASYNC16(sA + d,          a);
        CP_ASYNC16(sA + 16384 + d,  a + 1024);
        CP_ASYNC16(sB + d,          b);
        CP_ASYNC16(sB + 16384 + d,  b + 1024);
    }
}

// ---------------------------------------------------------------------------
// Mainloop: acc[fm][fn][4] += split(A[128xK]) * split(B[128xK])^T
// 8 warps as 2(m) x 4(n); warp tile 64m x 32n; 3 split passes (hh, lh, hl).
// ---------------------------------------------------------------------------
__device__ __forceinline__ void hmma_mainloop(uint32_t smem_base,
    const __nv_bfloat16* __restrict__ Arows,
    const __nv_bfloat16* __restrict__ Brows,
    float acc[4][4][4])
{
    const int tid  = threadIdx.x;
    const int lane = tid & 31, wid = tid >> 5;
    const int wm = wid >> 2, wn = wid & 3;

    // ldmatrix per-lane address constants
    const uint32_t aOff  = (uint32_t)((wm * 64 + (lane & 15)) * 128);
    const uint32_t aKb   = (uint32_t)((lane >> 4) * 16);
    const uint32_t bOff  = (uint32_t)((wn * 32 + ((lane >> 4) << 3) + (lane & 7)) * 128);
    const uint32_t bKb   = (uint32_t)(((lane >> 3) & 1) * 16);
    const uint32_t swz   = (uint32_t)((lane & 7) << 4);

    load_tiles(smem_base, smem_base + 32768, Arows, Brows, 0);
    CP_COMMIT();

    for (int c = 0; c < NCHUNK; ++c) {
        if (c + 1 < NCHUNK) {
            uint32_t st = smem_base + ((c + 1) & 1) * STAGE_BYTES;
            load_tiles(st, st + 32768, Arows, Brows, c + 1);
            CP_COMMIT();
            CP_WAIT1();
        } else {
            CP_WAIT0();
        }
        __syncthreads();

        const uint32_t bufA = smem_base + (c & 1) * STAGE_BYTES;
        const uint32_t bufB = bufA + 32768;

        #pragma unroll
        for (int ks = 0; ks < 4; ++ks) {
            uint32_t ahi[4][4], alo[4][4], bhi[2][4], blo[2][4];
            const uint32_t ak = (uint32_t)(ks * 32 + aKb) ^ swz;
            const uint32_t bk = (uint32_t)(ks * 32 + bKb) ^ swz;
            #pragma unroll
            for (int fm = 0; fm < 4; ++fm) {
                uint32_t ad = bufA + aOff + fm * 2048 + ak;
                LDSM4(ahi[fm][0], ahi[fm][1], ahi[fm][2], ahi[fm][3], ad);
                LDSM4(alo[fm][0], alo[fm][1], alo[fm][2], alo[fm][3], ad + 16384);
            }
            #pragma unroll
            for (int g = 0; g < 2; ++g) {
                uint32_t bd = bufB + bOff + g * 2048 + bk;
                LDSM4(bhi[g][0], bhi[g][1], bhi[g][2], bhi[g][3], bd);
                LDSM4(blo[g][0], blo[g][1], blo[g][2], blo[g][3], bd + 16384);
            }
            #pragma unroll
            for (int fm = 0; fm < 4; ++fm) {
                #pragma unroll
                for (int fn = 0; fn < 4; ++fn) {
                    const int g = fn >> 1, p = (fn & 1) * 2;
                    MMA16816(acc[fm][fn], ahi[fm], bhi[g][p], bhi[g][p + 1]);
                    MMA16816(acc[fm][fn], alo[fm], bhi[g][p], bhi[g][p + 1]);
                    MMA16816(acc[fm][fn], ahi[fm], blo[g][p], blo[g][p + 1]);
                }
            }
        }
        __syncthreads();
    }
}

// ---------------------------------------------------------------------------
// GEMM1: T = Daug @ U; epilogue adds bias (U row 1024) and re-splits to hi/lo.
// grid: (DD/TN = 8, BS_TOT/TM = 128)
// ---------------------------------------------------------------------------
__global__ __launch_bounds__(THREADS, 1)
void gemm1_tc(const __nv_bfloat16* __restrict__ A, const __nv_bfloat16* __restrict__ B,
              const float* __restrict__ Ubias, __nv_bfloat16* __restrict__ Tout)
{
    extern __shared__ char smem[];
    uint32_t smem_base = smem_u32_of(smem);

    const size_t mBase = (size_t)blockIdx.y * TM;
    const size_t nBase = (size_t)blockIdx.x * TN;

    float acc[4][4][4] = {};
    hmma_mainloop(smem_base, A + mBase * LDK, B + nBase * LDK, acc);

    const int lane = threadIdx.x & 31, wid = threadIdx.x >> 5;
    const int wm = wid >> 2, wn = wid & 3;

    #pragma unroll
    for (int fm = 0; fm < 4; ++fm) {
        const size_t r0 = mBase + wm * 64 + fm * 16 + (lane >> 2);
        #pragma unroll
        for (int fn = 0; fn < 4; ++fn) {
            const size_t n = nBase + wn * 32 + fn * 8 + 2 * (lane & 3);
            const float b0 = Ubias[n], b1 = Ubias[n + 1];
            #pragma unroll
            for (int h = 0; h < 2; ++h) {
                const size_t r = r0 + h * 8;
                float f0 = acc[fm][fn][2 * h]     + b0;
                float f1 = acc[fm][fn][2 * h + 1] + b1;
                __nv_bfloat16 h0, h1;
                uint32_t ph = pack_hi2(f0, f1, h0, h1);
                uint32_t pl = pack_lo2(f0, f1, h0, h1);
                *(uint32_t*)(Tout + r * LDK + n)        = ph;
                *(uint32_t*)(Tout + r * LDK + 1024 + n) = pl;
            }
        }
    }
}

// ---------------------------------------------------------------------------
// GEMM2: out[b,x,y] = T[b,x,:].H[b,y,:] + rowlin[b,x] + collin[b,y]
// grid: (SEQ/TN = 4, SEQ/TM = 4, BATCH)
// ---------------------------------------------------------------------------
__global__ __launch_bounds__(THREADS, 1)
void gemm2_tc(const __nv_bfloat16* __restrict__ A, const __nv_bfloat16* __restrict__ B,
              const float* __restrict__ rowlin, const float* __restrict__ collin,
              float* __restrict__ out)
{
    extern __shared__ char smem[];
    uint32_t smem_base = smem_u32_of(smem);

    const int b = blockIdx.z;
    const size_t xBase = (size_t)blockIdx.y * TM;
    const size_t yBase = (size_t)blockIdx.x * TN;

    float acc[4][4][4] = {};
    hmma_mainloop(smem_base,
                  A + ((size_t)b * SEQ + xBase) * LDK,
                  B + ((size_t)b * SEQ + yBase) * LDK, acc);

    const int lane = threadIdx.x & 31, wid = threadIdx.x >> 5;
    const int wm = wid >> 2, wn = wid & 3;

    #pragma unroll
    for (int fm = 0; fm < 4; ++fm) {
        const size_t x0 = xBase + wm * 64 + fm * 16 + (lane >> 2);
        #pragma unroll
        for (int h = 0; h < 2; ++h) {
            const size_t gx = (size_t)b * SEQ + x0 + h * 8;
            const float rl = rowlin[gx];
            #pragma unroll
            for (int fn = 0; fn < 4; ++fn) {
                const size_t y = yBase + wn * 32 + fn * 8 + 2 * (lane & 3);
                const float c0 = collin[(size_t)b * SEQ + y];
                const float c1 = collin[(size_t)b * SEQ + y + 1];
                float2 o;
                o.x = acc[fm][fn][2 * h]     + rl + c0;
                o.y = acc[fm][fn][2 * h + 1] + rl + c1;
                *(float2*)(out + gx * SEQ + y) = o;
            }
        }
    }
}

// ---------------------------------------------------------------------------
// Fused prep: split(D) + split(H) + rowlin/collin in one pass.
// One warp per row; 2048 blocks x 256 threads (8 warps).
// ---------------------------------------------------------------------------
__global__ __launch_bounds__(256)
void prep_kernel(const float* __restrict__ D, const float* __restrict__ H,
                 const float* __restrict__ W,
                 __nv_bfloat16* __restrict__ Ds, __nv_bfloat16* __restrict__ Hs,
                 float* __restrict__ rowlin, float* __restrict__ collin)
{
    const int warp = threadIdx.x >> 5, lane = threadIdx.x & 31;
    const size_t m = (size_t)blockIdx.x * 8 + warp;
    const float* drow = D + m * DD;
    const float* hrow = H + m * DD;
    __nv_bfloat16* dsp = g_Ds == Ds ? Ds + m * LDK : Ds + m * LDK;  // keep simple
    __nv_bfloat16* dd = Ds + m * LDK;
    __nv_bfloat16* dh = Hs + m * LDK;
    (void)dsp;

    float s1 = 0.f, s2 = 0.f;
    #pragma unroll
    for (int i = 0; i < 8; ++i) {
        const int c = i * 128 + lane * 4;
        float4 dv = *(const float4*)(drow + c);
        float4 hv = *(const float4*)(hrow + c);
        float4 wv = *(const float4*)(W + c);              // aligned: W[0:1024]
        // W2 is offset by 1025 -> misaligned for float4; scalar loads (L1/L2 hit)
        float w20 = __ldg(W + DD + 1 + c);
        float w21 = __ldg(W + DD + 2 + c);
        float w22 = __ldg(W + DD + 3 + c);
        float w23 = __ldg(W + DD + 4 + c);

        s1 = fmaf(dv.x, wv.x, fmaf(dv.y, wv.y, fmaf(dv.z, wv.z, fmaf(dv.w, wv.w, s1))));
        s2 = fmaf(hv.x, w20, fmaf(hv.y, w21, fmaf(hv.z, w22, fmaf(hv.w, w23, s2))));

        store_split4(dd + c, dv);
        store_split4(dh + c, hv);
    }
    #pragma unroll
    for (int o = 16; o > 0; o >>= 1) {
        s1 += __shfl_down_sync(0xffffffffu, s1, o);
        s2 += __shfl_down_sync(0xffffffffu, s2, o);
    }
    if (lane == 0) {
        rowlin[m] = s1 + W[DD];
        collin[m] = s2;
    }
}

// Transpose + split U[0:1024][1024] -> Ut_split[1024][2048]
__global__ __launch_bounds__(256)
void transU_kernel(const float* __restrict__ U, __nv_bfloat16* __restrict__ Ut)
{
    __shared__ float t[32][33];
    const int k0 = blockIdx.y * 32, n0 = blockIdx.x * 32;
    const int tx = threadIdx.x, ty = threadIdx.y;   // block (32, 8)
    #pragma unroll
    for (int i = ty; i < 32; i += 8)
        t[i][tx] = U[(size_t)(k0 + i) * DD + n0 + tx];
    __syncthreads();
    #pragma unroll
    for (int i = ty; i < 32; i += 8) {
        const size_t n = n0 + i, k = k0 + tx;
        float f = t[tx][i];
        __nv_bfloat16 h = __float2bfloat16_rn(f);
        __nv_bfloat16 l = __float2bfloat16_rn(f - __bfloat162float(h));
        Ut[n * LDK + k]        = h;
        Ut[n * LDK + 1024 + k] = l;
    }
}

// ---------------------------------------------------------------------------
extern "C" void kernel_launch(void* const* d_in, const int* in_sizes, int n_in,
                              void* d_out, int out_size)
{
    const float* D = (const float*)d_in[0];   // [32,512,1024]
    const float* H = (const float*)d_in[1];   // [32,512,1024]
    const float* U = (const float*)d_in[2];   // [1025,1024]
    const float* W = (const float*)d_in[3];   // [2049]
    float* out = (float*)d_out;               // [32,512,512]

    __nv_bfloat16 *Ds, *Hs, *Ts, *Uts;
    float *rowlin, *collin;
    cudaGetSymbolAddress((void**)&Ds,  g_Ds);
    cudaGetSymbolAddress((void**)&Hs,  g_Hs);
    cudaGetSymbolAddress((void**)&Ts,  g_Ts);
    cudaGetSymbolAddress((void**)&Uts, g_Uts);
    cudaGetSymbolAddress((void**)&rowlin, g_rowlin);
    cudaGetSymbolAddress((void**)&collin, g_collin);

    cudaFuncSetAttribute(gemm1_tc, cudaFuncAttributeMaxDynamicSharedMemorySize, SMEM_TOTAL);
    cudaFuncSetAttribute(gemm2_tc, cudaFuncAttributeMaxDynamicSharedMemorySize, SMEM_TOTAL);

    // fused prep: split(D), split(H), rowlin, collin — one pass over D and H
    prep_kernel<<<BS_TOT / 8, 256>>>(D, H, W, Ds, Hs, rowlin, collin);
    transU_kernel<<<dim3(32, 32), dim3(32, 8)>>>(U, Uts);

    // GEMM1: T = Daug @ U
    gemm1_tc<<<dim3(DD / TN, BS_TOT / TM), THREADS, SMEM_TOTAL>>>(
        Ds, Uts, U + (size_t)DD * DD, Ts);

    // GEMM2: out = T @ H^T + rowlin + collin
    gemm2_tc<<<dim3(SEQ / TN, SEQ / TM, BATCH), THREADS, SMEM_TOTAL>>>(
        Ts, Hs, rowlin, collin, out);
}

// round 5
// speedup vs baseline: 3.9275x; 1.0171x over previous
#include <cuda_runtime.h>
#include <cuda_bf16.h>
#include <cstdint>

#define BATCH 32
#define SEQ   512
#define DD    1024
#define BS_TOT (BATCH*SEQ)      // 16384
#define LDK   2048              // split row stride: hi at [0,1024), lo at [1024,2048)
#define TM    128
#define TN    128
#define KTILE 64
#define NCHUNK (DD/KTILE)       // 16
#define THREADS 256

// SMEM: per stage A(hi,lo) 32KB + B(hi,lo) 32KB = 64KB; 3 stages = 192KB
#define STAGE_BYTES 65536
#define NSTAGE 3
#define SMEM_TOTAL  (NSTAGE*STAGE_BYTES)

// ---------------- scratch (static __device__, allocation-free) ----------------
__device__ __nv_bfloat16 g_Ds [(size_t)BS_TOT * LDK];
__device__ __nv_bfloat16 g_Hs [(size_t)BS_TOT * LDK];
__device__ __nv_bfloat16 g_Ts [(size_t)BS_TOT * LDK];
__device__ __nv_bfloat16 g_Uts[(size_t)DD     * LDK];
__device__ float g_rowlin[BS_TOT];
__device__ float g_collin[BS_TOT];

// ---------------- PTX helpers (family-portable: sm_80+) ----------------
#define CP_ASYNC16(smem_u32, gptr) \
    asm volatile("cp.async.cg.shared.global [%0], [%1], 16;" :: "r"(smem_u32), "l"(gptr))
#define CP_COMMIT()  asm volatile("cp.async.commit_group;" ::: "memory")
#define CP_WAIT0()   asm volatile("cp.async.wait_group 0;" ::: "memory")
#define CP_WAIT1()   asm volatile("cp.async.wait_group 1;" ::: "memory")

#define LDSM4(r0,r1,r2,r3,addr) \
    asm volatile("ldmatrix.sync.aligned.m8n8.x4.shared.b16 {%0,%1,%2,%3}, [%4];" \
        : "=r"(r0),"=r"(r1),"=r"(r2),"=r"(r3) : "r"(addr))

#define MMA16816(d, a, b0, b1) \
    asm volatile("mma.sync.aligned.m16n8k16.row.col.f32.bf16.bf16.f32 " \
        "{%0,%1,%2,%3}, {%4,%5,%6,%7}, {%8,%9}, {%0,%1,%2,%3};" \
        : "+f"((d)[0]),"+f"((d)[1]),"+f"((d)[2]),"+f"((d)[3]) \
        : "r"((a)[0]),"r"((a)[1]),"r"((a)[2]),"r"((a)[3]),"r"((b0)),"r"((b1)))

__device__ __forceinline__ uint32_t smem_u32_of(const void* p) {
    uint32_t a;
    asm("{ .reg .u64 t; cvta.to.shared.u64 t, %1; cvt.u32.u64 %0, t; }" : "=r"(a) : "l"(p));
    return a;
}

__device__ __forceinline__ uint32_t pack_hi2(float f0, float f1,
                                             __nv_bfloat16& h0, __nv_bfloat16& h1) {
    h0 = __float2bfloat16_rn(f0);
    h1 = __float2bfloat16_rn(f1);
    return (uint32_t)__bfloat16_as_ushort(h0) | ((uint32_t)__bfloat16_as_ushort(h1) << 16);
}
__device__ __forceinline__ uint32_t pack_lo2(float f0, float f1,
                                             __nv_bfloat16 h0, __nv_bfloat16 h1) {
    __nv_bfloat16 l0 = __float2bfloat16_rn(f0 - __bfloat162float(h0));
    __nv_bfloat16 l1 = __float2bfloat16_rn(f1 - __bfloat162float(h1));
    return (uint32_t)__bfloat16_as_ushort(l0) | ((uint32_t)__bfloat16_as_ushort(l1) << 16);
}

__device__ __forceinline__ void store_split4(__nv_bfloat16* dst, float4 v) {
    __nv_bfloat16 h0, h1, h2, h3;
    uint32_t hA = pack_hi2(v.x, v.y, h0, h1);
    uint32_t hB = pack_hi2(v.z, v.w, h2, h3);
    uint32_t lA = pack_lo2(v.x, v.y, h0, h1);
    uint32_t lB = pack_lo2(v.z, v.w, h2, h3);
    *(uint2*)dst          = make_uint2(hA, hB);
    *(uint2*)(dst + 1024) = make_uint2(lA, lB);
}

// ---------------------------------------------------------------------------
// cp.async tile loader: A tile 128 rows x 64 bf16 (hi+lo), B tile same.
// SW128 swizzle: addr = row*128 + (kb ^ ((row&7)<<4)) — store & ldmatrix agree.
// ---------------------------------------------------------------------------
__device__ __forceinline__ void load_tiles(uint32_t stage_base,
    const __nv_bfloat16* __restrict__ A, const __nv_bfloat16* __restrict__ B, int c)
{
    const uint32_t sA = stage_base, sB = stage_base + 32768;
    const int tid = threadIdx.x;
    #pragma unroll
    for (int i = 0; i < 4; ++i) {
        int idx = tid + i * THREADS;          // 0..1023
        int row = idx >> 3, j = idx & 7;      // 128 rows x 8 (16B each)
        uint32_t d = (uint32_t)(row * 128 + ((j * 16) ^ ((row & 7) << 4)));
        const __nv_bfloat16* a = A + (size_t)row * LDK + c * KTILE + j * 8;
        const __nv_bfloat16* b = B + (size_t)row * LDK + c * KTILE + j * 8;
        CP_ASYNC16(sA + d,          a);
        CP_ASYNC16(sA + 16384 + d,  a + 1024);
        CP_ASYNC16(sB + d,          b);
        CP_ASYNC16(sB + 16384 + d,  b + 1024);
    }
}

// ldmatrix all fragments for one k-step into register buffers
__device__ __forceinline__ void ldsm_frags(uint32_t bufA, uint32_t bufB,
    uint32_t aOff, uint32_t bOff, uint32_t ak, uint32_t bk,
    uint32_t ahi[4][4], uint32_t alo[4][4], uint32_t bhi[2][4], uint32_t blo[2][4])
{
    #pragma unroll
    for (int fm = 0; fm < 4; ++fm) {
        uint32_t ad = bufA + aOff + fm * 2048 + ak;
        LDSM4(ahi[fm][0], ahi[fm][1], ahi[fm][2], ahi[fm][3], ad);
        LDSM4(alo[fm][0], alo[fm][1], alo[fm][2], alo[fm][3], ad + 16384);
    }
    #pragma unroll
    for (int g = 0; g < 2; ++g) {
        uint32_t bd = bufB + bOff + g * 2048 + bk;
        LDSM4(bhi[g][0], bhi[g][1], bhi[g][2], bhi[g][3], bd);
        LDSM4(blo[g][0], blo[g][1], blo[g][2], blo[g][3], bd + 16384);
    }
}

// ---------------------------------------------------------------------------
// Mainloop: acc[fm][fn][4] += split(A[128xK]) * split(B[128xK])^T
// 8 warps as 2(m) x 4(n); warp tile 64m x 32n; 3 split passes (hh, lh, hl).
// 3-stage cp.async pipeline + register double-buffered ldmatrix fragments.
// ---------------------------------------------------------------------------
__device__ __forceinline__ void hmma_mainloop(uint32_t smem_base,
    const __nv_bfloat16* __restrict__ Arows,
    const __nv_bfloat16* __restrict__ Brows,
    float acc[4][4][4])
{
    const int tid  = threadIdx.x;
    const int lane = tid & 31, wid = tid >> 5;
    const int wm = wid >> 2, wn = wid & 3;

    // ldmatrix per-lane address constants
    const uint32_t aOff  = (uint32_t)((wm * 64 + (lane & 15)) * 128);
    const uint32_t aKb   = (uint32_t)((lane >> 4) * 16);
    const uint32_t bOff  = (uint32_t)((wn * 32 + ((lane >> 4) << 3) + (lane & 7)) * 128);
    const uint32_t bKb   = (uint32_t)(((lane >> 3) & 1) * 16);
    const uint32_t swz   = (uint32_t)((lane & 7) << 4);

    load_tiles(smem_base,               Arows, Brows, 0); CP_COMMIT();
    load_tiles(smem_base + STAGE_BYTES, Arows, Brows, 1); CP_COMMIT();

    uint32_t ahi[2][4][4], alo[2][4][4], bhi[2][2][4], blo[2][2][4];

    for (int c = 0; c < NCHUNK; ++c) {
        if (c + 1 < NCHUNK) { CP_WAIT1(); } else { CP_WAIT0(); }
        __syncthreads();                       // all warps done reading stage (c-1)%3
        if (c + 2 < NCHUNK) {                  // prefetch c+2 into stage (c+2)%3
            load_tiles(smem_base + ((c + 2) % NSTAGE) * STAGE_BYTES, Arows, Brows, c + 2);
            CP_COMMIT();
        }

        const uint32_t bufA = smem_base + (c % NSTAGE) * STAGE_BYTES;
        const uint32_t bufB = bufA + 32768;

        // prime k-step 0 fragments
        ldsm_frags(bufA, bufB, aOff, bOff, aKb ^ swz, bKb ^ swz,
                   ahi[0], alo[0], bhi[0], blo[0]);

        #pragma unroll
        for (int ks = 0; ks < 4; ++ks) {
            const int cur = ks & 1, nxt = cur ^ 1;
            if (ks < 3) {                      // prefetch ks+1 frags before mma of ks
                const uint32_t ak = (uint32_t)((ks + 1) * 32 + aKb) ^ swz;
                const uint32_t bk = (uint32_t)((ks + 1) * 32 + bKb) ^ swz;
                ldsm_frags(bufA, bufB, aOff, bOff, ak, bk,
                           ahi[nxt], alo[nxt], bhi[nxt], blo[nxt]);
            }
            #pragma unroll
            for (int fm = 0; fm < 4; ++fm) {
                #pragma unroll
                for (int fn = 0; fn < 4; ++fn) {
                    const int g = fn >> 1, p = (fn & 1) * 2;
                    MMA16816(acc[fm][fn], ahi[cur][fm], bhi[cur][g][p], bhi[cur][g][p + 1]);
                    MMA16816(acc[fm][fn], alo[cur][fm], bhi[cur][g][p], bhi[cur][g][p + 1]);
                    MMA16816(acc[fm][fn], ahi[cur][fm], blo[cur][g][p], blo[cur][g][p + 1]);
                }
            }
        }
    }
    __syncthreads();
}

// ---------------------------------------------------------------------------
// GEMM1: T = Daug @ U; epilogue adds bias (U row 1024) and re-splits to hi/lo.
// grid: (DD/TN = 8, BS_TOT/TM = 128)
// ---------------------------------------------------------------------------
__global__ __launch_bounds__(THREADS, 1)
void gemm1_tc(const __nv_bfloat16* __restrict__ A, const __nv_bfloat16* __restrict__ B,
              const float* __restrict__ Ubias, __nv_bfloat16* __restrict__ Tout)
{
    extern __shared__ char smem[];
    uint32_t smem_base = smem_u32_of(smem);

    const size_t mBase = (size_t)blockIdx.y * TM;
    const size_t nBase = (size_t)blockIdx.x * TN;

    float acc[4][4][4] = {};
    hmma_mainloop(smem_base, A + mBase * LDK, B + nBase * LDK, acc);

    const int lane = threadIdx.x & 31, wid = threadIdx.x >> 5;
    const int wm = wid >> 2, wn = wid & 3;

    #pragma unroll
    for (int fm = 0; fm < 4; ++fm) {
        const size_t r0 = mBase + wm * 64 + fm * 16 + (lane >> 2);
        #pragma unroll
        for (int fn = 0; fn < 4; ++fn) {
            const size_t n = nBase + wn * 32 + fn * 8 + 2 * (lane & 3);
            const float b0 = Ubias[n], b1 = Ubias[n + 1];
            #pragma unroll
            for (int h = 0; h < 2; ++h) {
                const size_t r = r0 + h * 8;
                float f0 = acc[fm][fn][2 * h]     + b0;
                float f1 = acc[fm][fn][2 * h + 1] + b1;
                __nv_bfloat16 h0, h1;
                uint32_t ph = pack_hi2(f0, f1, h0, h1);
                uint32_t pl = pack_lo2(f0, f1, h0, h1);
                *(uint32_t*)(Tout + r * LDK + n)        = ph;
                *(uint32_t*)(Tout + r * LDK + 1024 + n) = pl;
            }
        }
    }
}

// ---------------------------------------------------------------------------
// GEMM2: out[b,x,y] = T[b,x,:].H[b,y,:] + rowlin[b,x] + collin[b,y]
// grid: (SEQ/TN = 4, SEQ/TM = 4, BATCH)
// ---------------------------------------------------------------------------
__global__ __launch_bounds__(THREADS, 1)
void gemm2_tc(const __nv_bfloat16* __restrict__ A, const __nv_bfloat16* __restrict__ B,
              const float* __restrict__ rowlin, const float* __restrict__ collin,
              float* __restrict__ out)
{
    extern __shared__ char smem[];
    uint32_t smem_base = smem_u32_of(smem);

    const int b = blockIdx.z;
    const size_t xBase = (size_t)blockIdx.y * TM;
    const size_t yBase = (size_t)blockIdx.x * TN;

    float acc[4][4][4] = {};
    hmma_mainloop(smem_base,
                  A + ((size_t)b * SEQ + xBase) * LDK,
                  B + ((size_t)b * SEQ + yBase) * LDK, acc);

    const int lane = threadIdx.x & 31, wid = threadIdx.x >> 5;
    const int wm = wid >> 2, wn = wid & 3;

    #pragma unroll
    for (int fm = 0; fm < 4; ++fm) {
        const size_t x0 = xBase + wm * 64 + fm * 16 + (lane >> 2);
        #pragma unroll
        for (int h = 0; h < 2; ++h) {
            const size_t gx = (size_t)b * SEQ + x0 + h * 8;
            const float rl = rowlin[gx];
            #pragma unroll
            for (int fn = 0; fn < 4; ++fn) {
                const size_t y = yBase + wn * 32 + fn * 8 + 2 * (lane & 3);
                const float c0 = collin[(size_t)b * SEQ + y];
                const float c1 = collin[(size_t)b * SEQ + y + 1];
                float2 o;
                o.x = acc[fm][fn][2 * h]     + rl + c0;
                o.y = acc[fm][fn][2 * h + 1] + rl + c1;
                *(float2*)(out + gx * SEQ + y) = o;
            }
        }
    }
}

// ---------------------------------------------------------------------------
// Fused prep: split(D) + split(H) + rowlin/collin in one pass.
// One warp per row; 2048 blocks x 256 threads (8 warps).
// ---------------------------------------------------------------------------
__global__ __launch_bounds__(256)
void prep_kernel(const float* __restrict__ D, const float* __restrict__ H,
                 const float* __restrict__ W,
                 __nv_bfloat16* __restrict__ Ds, __nv_bfloat16* __restrict__ Hs,
                 float* __restrict__ rowlin, float* __restrict__ collin)
{
    const int warp = threadIdx.x >> 5, lane = threadIdx.x & 31;
    const size_t m = (size_t)blockIdx.x * 8 + warp;
    const float* drow = D + m * DD;
    const float* hrow = H + m * DD;
    __nv_bfloat16* dd = Ds + m * LDK;
    __nv_bfloat16* dh = Hs + m * LDK;

    float s1 = 0.f, s2 = 0.f;
    #pragma unroll
    for (int i = 0; i < 8; ++i) {
        const int c = i * 128 + lane * 4;
        float4 dv = *(const float4*)(drow + c);
        float4 hv = *(const float4*)(hrow + c);
        float4 wv = *(const float4*)(W + c);              // aligned: W[0:1024]
        float w20 = __ldg(W + DD + 1 + c);
        float w21 = __ldg(W + DD + 2 + c);
        float w22 = __ldg(W + DD + 3 + c);
        float w23 = __ldg(W + DD + 4 + c);

        s1 = fmaf(dv.x, wv.x, fmaf(dv.y, wv.y, fmaf(dv.z, wv.z, fmaf(dv.w, wv.w, s1))));
        s2 = fmaf(hv.x, w20, fmaf(hv.y, w21, fmaf(hv.z, w22, fmaf(hv.w, w23, s2))));

        store_split4(dd + c, dv);
        store_split4(dh + c, hv);
    }
    #pragma unroll
    for (int o = 16; o > 0; o >>= 1) {
        s1 += __shfl_down_sync(0xffffffffu, s1, o);
        s2 += __shfl_down_sync(0xffffffffu, s2, o);
    }
    if (lane == 0) {
        rowlin[m] = s1 + W[DD];
        collin[m] = s2;
    }
}

// Transpose + split U[0:1024][1024] -> Ut_split[1024][2048]
__global__ __launch_bounds__(256)
void transU_kernel(const float* __restrict__ U, __nv_bfloat16* __restrict__ Ut)
{
    __shared__ float t[32][33];
    const int k0 = blockIdx.y * 32, n0 = blockIdx.x * 32;
    const int tx = threadIdx.x, ty = threadIdx.y;   // block (32, 8)
    #pragma unroll
    for (int i = ty; i < 32; i += 8)
        t[i][tx] = U[(size_t)(k0 + i) * DD + n0 + tx];
    __syncthreads();
    #pragma unroll
    for (int i = ty; i < 32; i += 8) {
        const size_t n = n0 + i, k = k0 + tx;
        float f = t[tx][i];
        __nv_bfloat16 h = __float2bfloat16_rn(f);
        __nv_bfloat16 l = __float2bfloat16_rn(f - __bfloat162float(h));
        Ut[n * LDK + k]        = h;
        Ut[n * LDK + 1024 + k] = l;
    }
}

// ---------------------------------------------------------------------------
extern "C" void kernel_launch(void* const* d_in, const int* in_sizes, int n_in,
                              void* d_out, int out_size)
{
    const float* D = (const float*)d_in[0];   // [32,512,1024]
    const float* H = (const float*)d_in[1];   // [32,512,1024]
    const float* U = (const float*)d_in[2];   // [1025,1024]
    const float* W = (const float*)d_in[3];   // [2049]
    float* out = (float*)d_out;               // [32,512,512]

    __nv_bfloat16 *Ds, *Hs, *Ts, *Uts;
    float *rowlin, *collin;
    cudaGetSymbolAddress((void**)&Ds,  g_Ds);
    cudaGetSymbolAddress((void**)&Hs,  g_Hs);
    cudaGetSymbolAddress((void**)&Ts,  g_Ts);
    cudaGetSymbolAddress((void**)&Uts, g_Uts);
    cudaGetSymbolAddress((void**)&rowlin, g_rowlin);
    cudaGetSymbolAddress((void**)&collin, g_collin);

    cudaFuncSetAttribute(gemm1_tc, cudaFuncAttributeMaxDynamicSharedMemorySize, SMEM_TOTAL);
    cudaFuncSetAttribute(gemm2_tc, cudaFuncAttributeMaxDynamicSharedMemorySize, SMEM_TOTAL);

    // fused prep: split(D), split(H), rowlin, collin — one pass over D and H
    prep_kernel<<<BS_TOT / 8, 256>>>(D, H, W, Ds, Hs, rowlin, collin);
    transU_kernel<<<dim3(32, 32), dim3(32, 8)>>>(U, Uts);

    // GEMM1: T = Daug @ U
    gemm1_tc<<<dim3(DD / TN, BS_TOT / TM), THREADS, SMEM_TOTAL>>>(
        Ds, Uts, U + (size_t)DD * DD, Ts);

    // GEMM2: out = T @ H^T + rowlin + collin
    gemm2_tc<<<dim3(SEQ / TN, SEQ / TM, BATCH), THREADS, SMEM_TOTAL>>>(
        Ts, Hs, rowlin, collin, out);
}